// round 9
// baseline (speedup 1.0000x reference)
#include <cuda_runtime.h>
#include <cuda_fp16.h>
#include <cstdint>

#define D 128
#define T 256
#define NTILES 2048          // per axis: 1024 lines * 2 tiles of 128
#define SCALE 0.08838834764831845f   // 128^-0.5

typedef unsigned long long ull;

// Per-axis precomputed M^T (fp32): g_MT[c*128 + k] = (Wq^T Wk)[k,c] * SCALE
__device__ float g_MT_h[D * D];
__device__ float g_MT_w[D * D];

// ---- smem byte layout (all fp16 tiles at 272B row pitch = 136 halves) ----
#define OFF_MH 0                       // fp16 M [128][136]
#define OFF_XH 34816                   // fp16 X [128][136]
#define OFF_KF 69632                   // fp16 KV [130][136]
#define OFF_PT 104992                  // partials [3][128][2] fp32
#define OFF_DT 108064                  // weights  [128][4] fp32
#define SMEM_TOTAL 110112              // x2 CTAs = 220224 B/SM

// ---------------------------------------------------------------------------
__device__ __forceinline__ uint32_t smem_u32(const void* p) {
    uint32_t a;
    asm("{ .reg .u64 t; cvta.to.shared.u64 t, %1; cvt.u32.u64 %0, t; }"
        : "=r"(a) : "l"(p));
    return a;
}
__device__ __forceinline__ void ldsm4(uint32_t* r, uint32_t a) {
    asm volatile("ldmatrix.sync.aligned.m8n8.x4.shared.b16 {%0,%1,%2,%3}, [%4];"
                 : "=r"(r[0]), "=r"(r[1]), "=r"(r[2]), "=r"(r[3]) : "r"(a));
}
__device__ __forceinline__ void mmah(float* d, const uint32_t* a,
                                     uint32_t b0, uint32_t b1) {
    asm volatile(
        "mma.sync.aligned.m16n8k16.row.col.f32.f16.f16.f32 "
        "{%0,%1,%2,%3},{%4,%5,%6,%7},{%8,%9},{%0,%1,%2,%3};"
        : "+f"(d[0]), "+f"(d[1]), "+f"(d[2]), "+f"(d[3])
        : "r"(a[0]), "r"(a[1]), "r"(a[2]), "r"(a[3]), "r"(b0), "r"(b1));
}
__device__ __forceinline__ ull pack4h(float4 v) {
    __half2 h0 = __floats2half2_rn(v.x, v.y);
    __half2 h1 = __floats2half2_rn(v.z, v.w);
    unsigned u0 = *(unsigned*)&h0, u1 = *(unsigned*)&h1;
    return (ull)u0 | ((ull)u1 << 32);
}

// ---------------------------------------------------------------------------
// Kernel 1: M^T[c][k] = sum_e Wq[e,k] * Wk[e,c] * SCALE  (per axis)
// ---------------------------------------------------------------------------
__global__ void compute_M_kernel(const float* __restrict__ Wq_h,
                                 const float* __restrict__ Wk_h,
                                 const float* __restrict__ Wq_w,
                                 const float* __restrict__ Wk_w) {
    int k = blockIdx.x, c = threadIdx.x, axis = blockIdx.y;
    const float* Wq = axis ? Wq_h : Wq_w;
    const float* Wk = axis ? Wk_h : Wk_w;
    float*       MT = axis ? g_MT_h : g_MT_w;
    __shared__ float sq[D];
    sq[c] = Wq[c * D + k];
    __syncthreads();
    float s = 0.f;
#pragma unroll 8
    for (int e = 0; e < D; e++) s = fmaf(sq[e], Wk[e * D + c], s);
    MT[c * D + k] = s * SCALE;
}

// ---------------------------------------------------------------------------
// Kernel 2: persistent HMMA fused axial attention, 2 CTAs/SM
// ---------------------------------------------------------------------------
template <int AXIS_H>
__global__ __launch_bounds__(256, 2)
void axial_mma(const float* __restrict__ x, const float* __restrict__ kv,
               float* __restrict__ out) {
    extern __shared__ char sm[];
    const uint32_t sb = smem_u32(sm);
    const int tid = threadIdx.x, wid = tid >> 5, lane = tid & 31;
    const int rg = wid >> 1, cg = wid & 1;       // row-group, col-group
    const int qrow = lane >> 2, qc = lane & 3;

    // ---- stage M^T (fp16) once per CTA ----
    {
        const float4* MT4 = (const float4*)(AXIS_H ? g_MT_h : g_MT_w);
        for (int s = tid; s < D * 32; s += 256) {
            int r = s >> 5, c8 = (s & 31) * 8;
            *(ull*)(sm + OFF_MH + r * 272 + c8) = pack4h(MT4[s]);
        }
    }

    auto tile_base = [](int t, int& base, int& sp, int& p0) {
        int line = t >> 1;
        p0 = (t & 1) * 128;
        if (AXIS_H) {
            int b = line >> 8, w = line & 255;
            base = b * (T * T * D) + w * D;
            sp   = T * D;
        } else {
            base = line * (T * D);
            sp   = D;
        }
    };

    // ---- X staging: 4096 float4, chunks of 8/thread ----
    auto x_ld8 = [&](int t, int g, float4* v) {
        int base, sp, p0; tile_base(t, base, sp, p0);
#pragma unroll
        for (int u = 0; u < 8; u++) {
            int s = tid + (g * 8 + u) * 256;
            int rl = s >> 5, c4 = s & 31;
            v[u] = __ldg((const float4*)(x + base + (p0 + rl) * sp + c4 * 4));
        }
    };
    auto x_st8 = [&](int g, const float4* v) {
#pragma unroll
        for (int u = 0; u < 8; u++) {
            int s = tid + (g * 8 + u) * 256;
            int rl = s >> 5, c4 = s & 31;
            *(ull*)(sm + OFF_XH + (uint32_t)rl * 272 + (uint32_t)c4 * 8) =
                pack4h(v[u]);
        }
    };
    // ---- KV staging: 4160 float4 (130 rows), chunks of 8 + remainder ----
    auto kv_ld8 = [&](int t, int g, float4* v) {
        int base, sp, p0; tile_base(t, base, sp, p0);
#pragma unroll
        for (int u = 0; u < 8; u++) {
            int s = tid + (g * 8 + u) * 256;
            int rl = s >> 5, c4 = s & 31;
            int gp = p0 - 1 + rl;
            v[u] = make_float4(0.f, 0.f, 0.f, 0.f);
            if (gp >= 0 && gp < T)
                v[u] = __ldg((const float4*)(kv + base + gp * sp + c4 * 4));
        }
    };
    auto kv_st8 = [&](int g, const float4* v) {
#pragma unroll
        for (int u = 0; u < 8; u++) {
            int s = tid + (g * 8 + u) * 256;
            int rl = s >> 5, c4 = s & 31;
            *(ull*)(sm + OFF_KF + (uint32_t)rl * 272 + (uint32_t)c4 * 8) =
                pack4h(v[u]);
        }
    };
    auto kv_rem = [&](int t) {
        int s = tid + 4096;
        if (s < 4160) {
            int base, sp, p0; tile_base(t, base, sp, p0);
            int rl = s >> 5, c4 = s & 31;
            int gp = p0 - 1 + rl;
            float4 v = make_float4(0.f, 0.f, 0.f, 0.f);
            if (gp >= 0 && gp < T)
                v = __ldg((const float4*)(kv + base + gp * sp + c4 * 4));
            *(ull*)(sm + OFF_KF + (uint32_t)rl * 272 + (uint32_t)c4 * 8) =
                pack4h(v);
        }
    };

    // per-thread ldmatrix base offsets
    uint32_t aoff[2], boff[4];
#pragma unroll
    for (int mi = 0; mi < 2; mi++) {
        aoff[mi] = sb + OFF_XH
                 + (uint32_t)(32 * rg + 16 * mi + (lane & 15)) * 272
                 + ((uint32_t)(lane >> 4) << 4);
    }
#pragma unroll
    for (int ng = 0; ng < 4; ng++) {
        boff[ng] = sb + OFF_MH
                 + (uint32_t)(64 * cg + 16 * ng + ((lane >> 4) << 3) + (lane & 7)) * 272
                 + (((uint32_t)(lane >> 3) & 1) << 4);
    }

    const int t0 = blockIdx.x, stride = gridDim.x;

    // ---- prologue: X(t0), KV(t0) ----
    if (t0 < NTILES) {
        float4 v[8];
        x_ld8(t0, 0, v);  x_st8(0, v);
        x_ld8(t0, 1, v);  x_st8(1, v);
        kv_ld8(t0, 0, v); kv_st8(0, v);
        kv_ld8(t0, 1, v); kv_st8(1, v);
        kv_rem(t0);
    }
    __syncthreads();

    for (int t = t0; t < NTILES; t += stride) {
        const int tn = t + stride;
        const bool hn = tn < NTILES;
        int base, sp, p0; tile_base(t, base, sp, p0);

        // ---- GEMM: acc = X(fp16) @ M(fp16), fp32 accumulate ----
        float acc[2][8][4];
#pragma unroll
        for (int mi = 0; mi < 2; mi++)
#pragma unroll
            for (int nt = 0; nt < 8; nt++)
#pragma unroll
                for (int u = 0; u < 4; u++) acc[mi][nt][u] = 0.f;

#pragma unroll 1
        for (int ks = 0; ks < 8; ks++) {
            const uint32_t ko = (uint32_t)ks * 32;
            uint32_t ah[2][4], bh[4][4];
#pragma unroll
            for (int mi = 0; mi < 2; mi++) ldsm4(ah[mi], aoff[mi] + ko);
#pragma unroll
            for (int ng = 0; ng < 4; ng++) ldsm4(bh[ng], boff[ng] + ko);
#pragma unroll
            for (int mi = 0; mi < 2; mi++)
#pragma unroll
                for (int ng = 0; ng < 4; ng++) {
                    mmah(acc[mi][2 * ng],     ah[mi], bh[ng][0], bh[ng][1]);
                    mmah(acc[mi][2 * ng + 1], ah[mi], bh[ng][2], bh[ng][3]);
                }
        }
        __syncthreads();                 // XH reads done; KV(t) visible

        // ---- banded dots (interleaved with X(tn) restage) ----
        const __half2* KH = (const __half2*)(sm + OFF_KF);  // [row*68 + h2]
        float prt[12];
        float4 xs[8];
        if (hn) x_ld8(tn, 0, xs);        // LDG latency under dots mi=0
#pragma unroll
        for (int mi = 0; mi < 2; mi++) {
#pragma unroll
            for (int h = 0; h < 2; h++) {
                int r = 32 * rg + 16 * mi + 8 * h + qrow;
#pragma unroll
                for (int dd = 0; dd < 3; dd++) {
                    float s = 0.f;
#pragma unroll
                    for (int nt = 0; nt < 8; nt++) {
                        float2 kp = __half22float2(
                            KH[(r + dd) * 68 + 32 * cg + 4 * nt + qc]);
                        s = fmaf(acc[mi][nt][2 * h],     kp.x, s);
                        s = fmaf(acc[mi][nt][2 * h + 1], kp.y, s);
                    }
                    prt[(mi * 2 + h) * 3 + dd] = s;
                }
            }
            if (mi == 0 && hn) {
                x_st8(0, xs);            // consume chunk A
                x_ld8(tn, 1, xs);        // chunk B under dots mi=1
            }
        }
        if (hn) x_st8(1, xs);
#pragma unroll
        for (int i = 0; i < 12; i++) {
            float v = prt[i];
            v += __shfl_xor_sync(0xffffffffu, v, 1);
            v += __shfl_xor_sync(0xffffffffu, v, 2);
            prt[i] = v;
        }
        if (qc == 0) {
            float* PT = (float*)(sm + OFF_PT);
#pragma unroll
            for (int mi = 0; mi < 2; mi++)
#pragma unroll
                for (int h = 0; h < 2; h++) {
                    int r = 32 * rg + 16 * mi + 8 * h + qrow;
#pragma unroll
                    for (int dd = 0; dd < 3; dd++)
                        PT[(dd * 128 + r) * 2 + cg] = prt[(mi * 2 + h) * 3 + dd];
                }
        }
        __syncthreads();                 // PT ready; XH(tn) staged

        // ---- exact band softmax ----
        if (tid < 128) {
            const float* PT = (const float*)(sm + OFF_PT);
            float* DT = (float*)(sm + OFF_DT);
            int pos = tid, gp = p0 + pos;
            float d0 = PT[(0 * 128 + pos) * 2] + PT[(0 * 128 + pos) * 2 + 1];
            float d1 = PT[(1 * 128 + pos) * 2] + PT[(1 * 128 + pos) * 2 + 1];
            float d2 = PT[(2 * 128 + pos) * 2] + PT[(2 * 128 + pos) * 2 + 1];
            float m = d1;
            if (gp > 0)     m = fmaxf(m, d0);
            if (gp < T - 1) m = fmaxf(m, d2);
            float w0 = (gp > 0)     ? __expf(d0 - m) : 0.f;
            float w1 = __expf(d1 - m);
            float w2 = (gp < T - 1) ? __expf(d2 - m) : 0.f;
            float inv = 1.f / (w0 + w1 + w2);
            DT[pos * 4 + 0] = w0 * inv;
            DT[pos * 4 + 1] = w1 * inv;
            DT[pos * 4 + 2] = w2 * inv;
        }
        __syncthreads();                 // DT ready

        // ---- KV(tn) chunk-A loads issued under writeback ----
        float4 kva[8];
        if (hn) kv_ld8(tn, 0, kva);

        // ---- weighted kv sum -> global out (AXIS_H accumulates) ----
        {
            const float* DT = (const float*)(sm + OFF_DT);
            int pos = tid >> 1, hf = tid & 1;
            float a0 = DT[pos * 4 + 0];
            float a1 = DT[pos * 4 + 1];
            float a2 = DT[pos * 4 + 2];
            float4* go = (float4*)(out + base + (p0 + pos) * sp);
#pragma unroll
            for (int u = 0; u < 16; u++) {
                int c4 = hf * 16 + u;
                uint2 w0 = *(const uint2*)(sm + OFF_KF + (pos + 0) * 272 + c4 * 8);
                uint2 w1 = *(const uint2*)(sm + OFF_KF + (pos + 1) * 272 + c4 * 8);
                uint2 w2 = *(const uint2*)(sm + OFF_KF + (pos + 2) * 272 + c4 * 8);
                float2 f0a = __half22float2(*(__half2*)&w0.x);
                float2 f0b = __half22float2(*(__half2*)&w0.y);
                float2 f1a = __half22float2(*(__half2*)&w1.x);
                float2 f1b = __half22float2(*(__half2*)&w1.y);
                float2 f2a = __half22float2(*(__half2*)&w2.x);
                float2 f2b = __half22float2(*(__half2*)&w2.y);
                float4 r;
                r.x = a0 * f0a.x + a1 * f1a.x + a2 * f2a.x;
                r.y = a0 * f0a.y + a1 * f1a.y + a2 * f2a.y;
                r.z = a0 * f0b.x + a1 * f1b.x + a2 * f2b.x;
                r.w = a0 * f0b.y + a1 * f1b.y + a2 * f2b.y;
                if (AXIS_H) {
                    float4 o = go[c4];
                    r.x += o.x; r.y += o.y; r.z += o.z; r.w += o.w;
                }
                go[c4] = r;
            }
        }
        __syncthreads();                 // KF reads done

        // ---- KV(tn) stores + chunk B + remainder ----
        if (hn) {
            kv_st8(0, kva);
            kv_ld8(tn, 1, kva);
            kv_st8(1, kva);
            kv_rem(tn);
        }
        // no sync needed: next GEMM doesn't read KF; dots(tn) is after
        // the post-GEMM __syncthreads() of the next iteration.
    }
}

// ---------------------------------------------------------------------------
extern "C" void kernel_launch(void* const* d_in, const int* in_sizes, int n_in,
                              void* d_out, int out_size) {
    const float* x    = (const float*)d_in[0];
    const float* kv   = (const float*)d_in[1];
    const float* Wq_h = (const float*)d_in[2];
    const float* Wk_h = (const float*)d_in[3];
    const float* Wq_w = (const float*)d_in[4];
    const float* Wk_w = (const float*)d_in[5];
    float* out = (float*)d_out;

    cudaFuncSetAttribute(axial_mma<0>,
                         cudaFuncAttributeMaxDynamicSharedMemorySize, SMEM_TOTAL);
    cudaFuncSetAttribute(axial_mma<1>,
                         cudaFuncAttributeMaxDynamicSharedMemorySize, SMEM_TOTAL);

    int nsm = 148;
    cudaDeviceGetAttribute(&nsm, cudaDevAttrMultiProcessorCount, 0);
    if (nsm <= 0) nsm = 148;
    int grid = 2 * nsm;
    if (grid > NTILES) grid = NTILES;

    compute_M_kernel<<<dim3(128, 2), 128>>>(Wq_h, Wk_h, Wq_w, Wk_w);
    axial_mma<0><<<grid, 256, SMEM_TOTAL>>>(x, kv, out);   // width: writes
    axial_mma<1><<<grid, 256, SMEM_TOTAL>>>(x, kv, out);   // height: accumulates
}

// round 10
// speedup vs baseline: 2.2722x; 2.2722x over previous
#include <cuda_runtime.h>
#include <cuda_fp16.h>
#include <cstdint>

#define D 128
#define T 256
#define SCALE 0.08838834764831845f   // 128^-0.5

typedef unsigned long long ull;

// Packed fp16 M^T per axis: g_Mhf[axis][j][k] = (Wq^T Wk)[k,j] * SCALE
// axis 0 = W (width attention), axis 1 = H (height attention)
__device__ __half g_Mhf[2][D][D];

// ---- smem byte layout (all tiles at 272B row pitch) ----
#define OFF_M  0                 // fp16 M  [128][136h]           34816 B
#define OFF_X  34816             // fp16 X  [256 pts][136h]       69632 B
#define OFF_KV 104448            // fp16 KV [324 rows][136h]      88128 B
#define OFF_PT 192576            // fp32 partials [3][256][2]      6144 B
#define OFF_WW 198720            // fp32 W-axis weights [256][4]   4096 B
#define OFF_WH 202816            // fp32 H-axis weights [256][4]   4096 B
#define SMEM_TOTAL 206912

// ---------------------------------------------------------------------------
__device__ __forceinline__ uint32_t smem_u32(const void* p) {
    uint32_t a;
    asm("{ .reg .u64 t; cvta.to.shared.u64 t, %1; cvt.u32.u64 %0, t; }"
        : "=r"(a) : "l"(p));
    return a;
}
__device__ __forceinline__ void cpa16(uint32_t dst, const void* src) {
    asm volatile("cp.async.cg.shared.global [%0], [%1], 16;"
                 :: "r"(dst), "l"(src));
}
__device__ __forceinline__ void cpa_commit() {
    asm volatile("cp.async.commit_group;");
}
__device__ __forceinline__ void cpa_wait0() {
    asm volatile("cp.async.wait_group 0;" ::: "memory");
}
__device__ __forceinline__ void ldsm4(uint32_t* r, uint32_t a) {
    asm volatile("ldmatrix.sync.aligned.m8n8.x4.shared.b16 {%0,%1,%2,%3}, [%4];"
                 : "=r"(r[0]), "=r"(r[1]), "=r"(r[2]), "=r"(r[3]) : "r"(a));
}
__device__ __forceinline__ void mmah(float* d, const uint32_t* a,
                                     uint32_t b0, uint32_t b1) {
    asm volatile(
        "mma.sync.aligned.m16n8k16.row.col.f32.f16.f16.f32 "
        "{%0,%1,%2,%3},{%4,%5,%6,%7},{%8,%9},{%0,%1,%2,%3};"
        : "+f"(d[0]), "+f"(d[1]), "+f"(d[2]), "+f"(d[3])
        : "r"(a[0]), "r"(a[1]), "r"(a[2]), "r"(a[3]), "r"(b0), "r"(b1));
}
__device__ __forceinline__ ull pack4h(float4 v) {
    __half2 h0 = __floats2half2_rn(v.x, v.y);
    __half2 h1 = __floats2half2_rn(v.z, v.w);
    unsigned u0 = *(unsigned*)&h0, u1 = *(unsigned*)&h1;
    return (ull)u0 | ((ull)u1 << 32);
}

// ---------------------------------------------------------------------------
// Kernel 1: M^T[j][k] = sum_e Wq[e,k] * Wk[e,j] * SCALE  -> fp16 (per axis)
// ---------------------------------------------------------------------------
__global__ void compute_M_kernel(const float* __restrict__ Wq_h,
                                 const float* __restrict__ Wk_h,
                                 const float* __restrict__ Wq_w,
                                 const float* __restrict__ Wk_w) {
    int k = blockIdx.x, j = threadIdx.x, axis = blockIdx.y;
    const float* Wq = axis ? Wq_h : Wq_w;
    const float* Wk = axis ? Wk_h : Wk_w;
    __shared__ float sq[D];
    sq[j] = Wq[j * D + k];     // Wq column k (j plays 'e')
    __syncthreads();
    float s = 0.f;
#pragma unroll 8
    for (int e = 0; e < D; e++) s = fmaf(sq[e], Wk[e * D + j], s);
    g_Mhf[axis][j][k] = __float2half(s * SCALE);
}

// ---------------------------------------------------------------------------
// Kernel 2: fused both-axis axial attention over 16x16 spatial tiles.
// One CTA per tile: stage X + KV halo; GEMM q_w -> W-band softmax weights;
// GEMM q_h -> H-band weights; single combined output write (no out RMW).
// ---------------------------------------------------------------------------
__global__ __launch_bounds__(256, 1)
void axial_fused(const float* __restrict__ x, const float* __restrict__ kv,
                 float* __restrict__ out) {
    extern __shared__ char sm[];
    const uint32_t sb = smem_u32(sm);
    const int tid = threadIdx.x, wid = tid >> 5, lane = tid & 31;
    const int rg = wid >> 1, cg = wid & 1;
    const int qrow = lane >> 2, qc = lane & 3;

    const int t = blockIdx.x;
    const int b = t >> 8, th = (t >> 4) & 15, tw = t & 15;
    const int h0 = th * 16, w0 = tw * 16;
    const float* xb = x + ((b * 256 + h0) * 256 + w0) * 128;

    // ---- M_w via cp.async (axis 0) ----
    {
        const __half* Mg = &g_Mhf[0][0][0];
#pragma unroll
        for (int u = 0; u < 8; u++) {
            int s = tid + u * 256;   // 2048 x 16B chunks
            cpa16(sb + OFF_M + (uint32_t)(s >> 4) * 272 + (uint32_t)(s & 15) * 16,
                  Mg + (s >> 4) * 128 + (s & 15) * 8);
        }
        cpa_commit();
    }

    // ---- X tile: 256 points x 128ch, LDG fp32 -> fp16 smem ----
#pragma unroll 1
    for (int g = 0; g < 4; g++) {
        float4 v[8];
#pragma unroll
        for (int u = 0; u < 8; u++) {
            int s = tid + (g * 8 + u) * 256;
            int r = s >> 5, c4 = s & 31;
            v[u] = __ldg((const float4*)(xb + ((r >> 4) * 256 + (r & 15)) * 128 + c4 * 4));
        }
#pragma unroll
        for (int u = 0; u < 8; u++) {
            int s = tid + (g * 8 + u) * 256;
            int r = s >> 5, c4 = s & 31;
            *(ull*)(sm + OFF_X + (uint32_t)r * 272 + (uint32_t)c4 * 8) = pack4h(v[u]);
        }
    }

    // ---- KV halo: 324 rows (18x18), zero-filled outside image ----
    {
        const float4 z = make_float4(0.f, 0.f, 0.f, 0.f);
#pragma unroll 1
        for (int g = 0; g < 5; g++) {
            float4 v[8];
#pragma unroll
            for (int u = 0; u < 8; u++) {
                int s = tid + (g * 8 + u) * 256;
                int kvi = s >> 5, c4 = s & 31;
                int a = kvi / 18, bw = kvi - a * 18;
                int gh = h0 - 1 + a, gw = w0 - 1 + bw;
                bool ok = (gh >= 0) && (gh < T) && (gw >= 0) && (gw < T);
                v[u] = ok ? __ldg((const float4*)(kv + ((b * 256 + gh) * 256 + gw) * 128 + c4 * 4)) : z;
            }
#pragma unroll
            for (int u = 0; u < 8; u++) {
                int s = tid + (g * 8 + u) * 256;
                int kvi = s >> 5, c4 = s & 31;
                *(ull*)(sm + OFF_KV + (uint32_t)kvi * 272 + (uint32_t)c4 * 8) = pack4h(v[u]);
            }
        }
        int s = tid + 10240;     // remainder: 10368 total
        if (s < 10368) {
            int kvi = s >> 5, c4 = s & 31;
            int a = kvi / 18, bw = kvi - a * 18;
            int gh = h0 - 1 + a, gw = w0 - 1 + bw;
            bool ok = (gh >= 0) && (gh < T) && (gw >= 0) && (gw < T);
            float4 v = ok ? __ldg((const float4*)(kv + ((b * 256 + gh) * 256 + gw) * 128 + c4 * 4)) : z;
            *(ull*)(sm + OFF_KV + (uint32_t)kvi * 272 + (uint32_t)c4 * 8) = pack4h(v);
        }
    }

    cpa_wait0();
    __syncthreads();        // M_w, X, KV all staged & visible

    // ---- ldmatrix frag offsets (warp m64 x n64) ----
    uint32_t aoff[4], boff[4];
#pragma unroll
    for (int mi = 0; mi < 4; mi++)
        aoff[mi] = sb + OFF_X
                 + (uint32_t)(64 * rg + 16 * mi + (lane & 15)) * 272
                 + ((uint32_t)(lane >> 4) << 4);
#pragma unroll
    for (int ng = 0; ng < 4; ng++)
        boff[ng] = sb + OFF_M
                 + (uint32_t)(64 * cg + 16 * ng + ((lane >> 4) << 3) + (lane & 7)) * 272
                 + (((uint32_t)(lane >> 3) & 1) << 4);

    float acc[4][8][4];

    auto run_gemm = [&]() {
#pragma unroll
        for (int mi = 0; mi < 4; mi++)
#pragma unroll
            for (int nt = 0; nt < 8; nt++)
#pragma unroll
                for (int u = 0; u < 4; u++) acc[mi][nt][u] = 0.f;
#pragma unroll 1
        for (int ks = 0; ks < 8; ks++) {
            const uint32_t ko = (uint32_t)ks * 32;
            uint32_t ah[4][4], bh[4][4];
#pragma unroll
            for (int mi = 0; mi < 4; mi++) ldsm4(ah[mi], aoff[mi] + ko);
#pragma unroll
            for (int ng = 0; ng < 4; ng++) ldsm4(bh[ng], boff[ng] + ko);
#pragma unroll
            for (int mi = 0; mi < 4; mi++)
#pragma unroll
                for (int ng = 0; ng < 4; ng++) {
                    mmah(acc[mi][2 * ng],     ah[mi], bh[ng][0], bh[ng][1]);
                    mmah(acc[mi][2 * ng + 1], ah[mi], bh[ng][2], bh[ng][3]);
                }
        }
    };

    // banded dots from register acc vs KV halo; kstep = 1 (W) or 18 (H)
    auto run_dots = [&](int kstep) {
        const __half2* KH = (const __half2*)(sm + OFF_KV);   // [row*68 + h2]
        float prt[24];
#pragma unroll
        for (int mi = 0; mi < 4; mi++)
#pragma unroll
            for (int h = 0; h < 2; h++) {
                int r = 64 * rg + 16 * mi + 8 * h + qrow;
                int kvc = ((r >> 4) + 1) * 18 + (r & 15) + 1;
#pragma unroll
                for (int dd = 0; dd < 3; dd++) {
                    int kvrow = kvc + (dd - 1) * kstep;
                    float s = 0.f;
#pragma unroll
                    for (int nt = 0; nt < 8; nt++) {
                        float2 kp = __half22float2(
                            KH[kvrow * 68 + 32 * cg + 4 * nt + qc]);
                        s = fmaf(acc[mi][nt][2 * h],     kp.x, s);
                        s = fmaf(acc[mi][nt][2 * h + 1], kp.y, s);
                    }
                    prt[(mi * 2 + h) * 3 + dd] = s;
                }
            }
#pragma unroll
        for (int i = 0; i < 24; i++) {
            float v = prt[i];
            v += __shfl_xor_sync(0xffffffffu, v, 1);
            v += __shfl_xor_sync(0xffffffffu, v, 2);
            prt[i] = v;
        }
        if (qc == 0) {
            float* PT = (float*)(sm + OFF_PT);
#pragma unroll
            for (int mi = 0; mi < 4; mi++)
#pragma unroll
                for (int h = 0; h < 2; h++) {
                    int r = 64 * rg + 16 * mi + 8 * h + qrow;
#pragma unroll
                    for (int dd = 0; dd < 3; dd++)
                        PT[(dd * 256 + r) * 2 + cg] = prt[(mi * 2 + h) * 3 + dd];
                }
        }
    };

    // exact band softmax -> weight buffer (all 256 threads, 1 point each)
    auto run_softmax = [&](float* Wbuf, int isH) {
        const float* PT = (const float*)(sm + OFF_PT);
        int pos = tid;
        int gp = isH ? (h0 + (pos >> 4)) : (w0 + (pos & 15));
        float d0 = PT[(0 * 256 + pos) * 2] + PT[(0 * 256 + pos) * 2 + 1];
        float d1 = PT[(1 * 256 + pos) * 2] + PT[(1 * 256 + pos) * 2 + 1];
        float d2 = PT[(2 * 256 + pos) * 2] + PT[(2 * 256 + pos) * 2 + 1];
        float m = d1;
        if (gp > 0)     m = fmaxf(m, d0);
        if (gp < T - 1) m = fmaxf(m, d2);
        float w0e = (gp > 0)     ? __expf(d0 - m) : 0.f;
        float w1e = __expf(d1 - m);
        float w2e = (gp < T - 1) ? __expf(d2 - m) : 0.f;
        float inv = 1.f / (w0e + w1e + w2e);
        Wbuf[pos * 4 + 0] = w0e * inv;
        Wbuf[pos * 4 + 1] = w1e * inv;
        Wbuf[pos * 4 + 2] = w2e * inv;
    };

    // ---- W axis ----
    run_gemm();                                 // q_w (reads M_w)
    __syncthreads();                            // all M_w reads done
    {   // M_h cp.async into the same M buffer
        const __half* Mg = &g_Mhf[1][0][0];
#pragma unroll
        for (int u = 0; u < 8; u++) {
            int s = tid + u * 256;
            cpa16(sb + OFF_M + (uint32_t)(s >> 4) * 272 + (uint32_t)(s & 15) * 16,
                  Mg + (s >> 4) * 128 + (s & 15) * 8);
        }
        cpa_commit();
    }
    run_dots(1);                                // W neighbors: +-1 in halo
    __syncthreads();                            // PT ready
    run_softmax((float*)(sm + OFF_WW), 0);
    cpa_wait0();
    __syncthreads();                            // WW ready, M_h visible, PT free

    // ---- H axis ----
    run_gemm();                                 // q_h (reads M_h)
    run_dots(18);                               // H neighbors: +-18 in halo
    __syncthreads();                            // PT ready
    run_softmax((float*)(sm + OFF_WH), 1);
    __syncthreads();                            // WH ready

    // ---- combined output: out = sum of 5 weighted kv neighbors ----
    {
        const float* WW = (const float*)(sm + OFF_WW);
        const float* WH = (const float*)(sm + OFF_WH);
#pragma unroll
        for (int pp = 0; pp < 2; pp++) {
            int p  = pp * 128 + (tid >> 1);
            int hf = tid & 1;
            int hh = p >> 4, wv = p & 15;
            int kvc = (hh + 1) * 18 + wv + 1;
            float ww0 = WW[p * 4 + 0], ww1 = WW[p * 4 + 1], ww2 = WW[p * 4 + 2];
            float wh0 = WH[p * 4 + 0], wh1 = WH[p * 4 + 1], wh2 = WH[p * 4 + 2];
            float wc = ww1 + wh1;
            float4* go = (float4*)(out + ((b * 256 + h0 + hh) * 256 + (w0 + wv)) * 128);
#pragma unroll
            for (int u = 0; u < 16; u++) {
                int c4 = hf * 16 + u;
                uint2 aL = *(const uint2*)(sm + OFF_KV + (kvc - 1)  * 272 + c4 * 8);
                uint2 aC = *(const uint2*)(sm + OFF_KV + kvc        * 272 + c4 * 8);
                uint2 aR = *(const uint2*)(sm + OFF_KV + (kvc + 1)  * 272 + c4 * 8);
                uint2 aU = *(const uint2*)(sm + OFF_KV + (kvc - 18) * 272 + c4 * 8);
                uint2 aD = *(const uint2*)(sm + OFF_KV + (kvc + 18) * 272 + c4 * 8);
                float2 l0 = __half22float2(*(__half2*)&aL.x), l1 = __half22float2(*(__half2*)&aL.y);
                float2 c0 = __half22float2(*(__half2*)&aC.x), c1 = __half22float2(*(__half2*)&aC.y);
                float2 r0 = __half22float2(*(__half2*)&aR.x), r1 = __half22float2(*(__half2*)&aR.y);
                float2 u0 = __half22float2(*(__half2*)&aU.x), u1 = __half22float2(*(__half2*)&aU.y);
                float2 d0 = __half22float2(*(__half2*)&aD.x), d1 = __half22float2(*(__half2*)&aD.y);
                float4 r;
                r.x = ww0 * l0.x + wc * c0.x + ww2 * r0.x + wh0 * u0.x + wh2 * d0.x;
                r.y = ww0 * l0.y + wc * c0.y + ww2 * r0.y + wh0 * u0.y + wh2 * d0.y;
                r.z = ww0 * l1.x + wc * c1.x + ww2 * r1.x + wh0 * u1.x + wh2 * d1.x;
                r.w = ww0 * l1.y + wc * c1.y + ww2 * r1.y + wh0 * u1.y + wh2 * d1.y;
                go[c4] = r;
            }
        }
    }
}

// ---------------------------------------------------------------------------
extern "C" void kernel_launch(void* const* d_in, const int* in_sizes, int n_in,
                              void* d_out, int out_size) {
    const float* x    = (const float*)d_in[0];
    const float* kv   = (const float*)d_in[1];
    const float* Wq_h = (const float*)d_in[2];
    const float* Wk_h = (const float*)d_in[3];
    const float* Wq_w = (const float*)d_in[4];
    const float* Wk_w = (const float*)d_in[5];
    float* out = (float*)d_out;

    cudaFuncSetAttribute(axial_fused,
                         cudaFuncAttributeMaxDynamicSharedMemorySize, SMEM_TOTAL);

    compute_M_kernel<<<dim3(128, 2), 128>>>(Wq_h, Wk_h, Wq_w, Wk_w);
    axial_fused<<<1024, 256, SMEM_TOTAL>>>(x, kv, out);
}